// round 10
// baseline (speedup 1.0000x reference)
#include <cuda_runtime.h>
#include <cuda_bf16.h>

#define E_DIM 1024
#define B_DIM 32
#define NROWS (B_DIM * 1024)

// Scratch (no allocation allowed): intermediates of the 3-stage GEMV chain.
__device__ float g_t1[B_DIM * E_DIM];   // proj_heat
__device__ float g_t2[B_DIM * E_DIM];   // v
__device__ float g_a [B_DIM * E_DIM];   // attn_out per batch (broadcast over S)

// y[b,e] = sum_k x[b,k] * W[e,k] + bias[e]
// One warp computes one output column e for 16 batches, so each W row is read
// by only 2 warps (vs 32 in the naive layout): ~8MB L2/DRAM traffic per stage
// instead of 128MB. x (128KB) is L1/L2-resident. 2048 warps over 148 SMs gives
// ~3.5 warps/SMSP — enough to hide latency and approach the FMA-pipe floor.
// No inter-block synchronization anywhere: stream order is the dependency.
__global__ __launch_bounds__(256) void gemv_stage(
    const float* __restrict__ x,
    const float* __restrict__ W,
    const float* __restrict__ bias,
    float* __restrict__ y)
{
    const int lane = threadIdx.x & 31;
    const int wg   = blockIdx.x * 8 + (threadIdx.x >> 5);   // 0 .. 2047
    const int e    = wg >> 1;
    const int b0   = (wg & 1) * 16;

    const float4* __restrict__ w4 = (const float4*)(W + (size_t)e * E_DIM);
    const float4* __restrict__ x4 = (const float4*)x + (size_t)b0 * (E_DIM / 4);

    float acc[16];
#pragma unroll
    for (int b = 0; b < 16; b++) acc[b] = 0.0f;

#pragma unroll
    for (int i = 0; i < 8; i++) {
        const int idx = lane + 32 * i;
        float4 wv = w4[idx];
#pragma unroll
        for (int b = 0; b < 16; b++) {
            float4 xv = x4[(size_t)b * (E_DIM / 4) + idx];
            acc[b] += xv.x * wv.x + xv.y * wv.y + xv.z * wv.z + xv.w * wv.w;
        }
    }

#pragma unroll
    for (int off = 16; off; off >>= 1) {
#pragma unroll
        for (int b = 0; b < 16; b++)
            acc[b] += __shfl_xor_sync(0xFFFFFFFFu, acc[b], off);
    }

    if (lane == 0) {
        const float bi = bias[e];
#pragma unroll
        for (int b = 0; b < 16; b++)
            y[(size_t)(b0 + b) * E_DIM + e] = acc[b] + bi;
    }
}

// out[r,:] = LN(img[r,:] + a[b,:]) * gamma + beta.
// Warp processes 2 rows (same batch b): pass 1 streams 24 independent LDG.128
// computing raw moments; pass 2 re-reads img from L1 and stores. One-pass
// variance (var = E[x^2] - mu^2) is safe at these magnitudes (|x| ~ 1).
__global__ __launch_bounds__(256) void add_ln_kernel(
    const float* __restrict__ img,
    const float* __restrict__ gamma,
    const float* __restrict__ beta,
    float* __restrict__ out)
{
    const int lane = threadIdx.x & 31;
    const int t = blockIdx.x * 8 + (threadIdx.x >> 5);  // 0 .. 16383
    const int r0 = t * 2;                               // rows r0, r0+1 share b
    const int b  = r0 >> 10;

    const float4* __restrict__ x0 = (const float4*)img + (size_t)r0 * (E_DIM / 4);
    const float4* __restrict__ x1 = x0 + E_DIM / 4;
    const float4* __restrict__ ar = (const float4*)g_a + (size_t)b * (E_DIM / 4);

    float s0 = 0.f, ss0 = 0.f, s1 = 0.f, ss1 = 0.f;
#pragma unroll
    for (int i = 0; i < 8; i++) {
        const int idx = lane + 32 * i;
        float4 av = ar[idx];
        float4 u = x0[idx];
        u.x += av.x; u.y += av.y; u.z += av.z; u.w += av.w;
        s0  += u.x + u.y + u.z + u.w;
        ss0 += u.x * u.x + u.y * u.y + u.z * u.z + u.w * u.w;
        float4 v = x1[idx];
        v.x += av.x; v.y += av.y; v.z += av.z; v.w += av.w;
        s1  += v.x + v.y + v.z + v.w;
        ss1 += v.x * v.x + v.y * v.y + v.z * v.z + v.w * v.w;
    }
#pragma unroll
    for (int off = 16; off; off >>= 1) {
        s0  += __shfl_xor_sync(0xFFFFFFFFu, s0,  off);
        ss0 += __shfl_xor_sync(0xFFFFFFFFu, ss0, off);
        s1  += __shfl_xor_sync(0xFFFFFFFFu, s1,  off);
        ss1 += __shfl_xor_sync(0xFFFFFFFFu, ss1, off);
    }
    const float inv_n = 1.0f / (float)E_DIM;
    const float mu0 = s0 * inv_n;
    const float mu1 = s1 * inv_n;
    const float ri0 = rsqrtf(ss0 * inv_n - mu0 * mu0 + 1e-5f);
    const float ri1 = rsqrtf(ss1 * inv_n - mu1 * mu1 + 1e-5f);

    float4* __restrict__ o0 = (float4*)out + (size_t)r0 * (E_DIM / 4);
    float4* __restrict__ o1 = o0 + E_DIM / 4;
    const float4* __restrict__ g4 = (const float4*)gamma;
    const float4* __restrict__ b4 = (const float4*)beta;
#pragma unroll
    for (int i = 0; i < 8; i++) {
        const int idx = lane + 32 * i;
        float4 gv = g4[idx];
        float4 bv = b4[idx];
        float4 av = ar[idx];      // L1 hit (4KB per batch)
        float4 u = x0[idx];       // L1 hit (read in pass 1)
        float4 o;
        o.x = (u.x + av.x - mu0) * ri0 * gv.x + bv.x;
        o.y = (u.y + av.y - mu0) * ri0 * gv.y + bv.y;
        o.z = (u.z + av.z - mu0) * ri0 * gv.z + bv.z;
        o.w = (u.w + av.w - mu0) * ri0 * gv.w + bv.w;
        o0[idx] = o;
        float4 v = x1[idx];       // L1 hit
        o.x = (v.x + av.x - mu1) * ri1 * gv.x + bv.x;
        o.y = (v.y + av.y - mu1) * ri1 * gv.y + bv.y;
        o.z = (v.z + av.z - mu1) * ri1 * gv.z + bv.z;
        o.w = (v.w + av.w - mu1) * ri1 * gv.w + bv.w;
        o1[idx] = o;
    }
}

// Inputs: 0 img_feat, 1 heat_feat, 2 W_img, 3 b_img, 4 W_heat, 5 b_heat,
// 6 Wq, 7 bq, 8 Wk, 9 bk, 10 Wv, 11 bv, 12 Wo, 13 bo, 14 gamma, 15 beta.
// KV seq len == 1 -> softmax == 1 -> img/Q projections are dead code, and
// attn_out is one vector per batch broadcast over all S tokens.
extern "C" void kernel_launch(void* const* d_in, const int* in_sizes, int n_in,
                              void* d_out, int out_size)
{
    const float* img_feat  = (const float*)d_in[0];
    const float* heat_feat = (const float*)d_in[1];
    const float* W_heat    = (const float*)d_in[4];
    const float* b_heat    = (const float*)d_in[5];
    const float* Wv        = (const float*)d_in[10];
    const float* bv        = (const float*)d_in[11];
    const float* Wo        = (const float*)d_in[12];
    const float* bo        = (const float*)d_in[13];
    const float* gamma     = (const float*)d_in[14];
    const float* beta      = (const float*)d_in[15];
    float* out = (float*)d_out;

    float *t1, *t2, *a;
    cudaGetSymbolAddress((void**)&t1, g_t1);
    cudaGetSymbolAddress((void**)&t2, g_t2);
    cudaGetSymbolAddress((void**)&a,  g_a);

    // 3 dependent GEMV stages; stream ordering is the synchronization.
    gemv_stage<<<256, 256>>>(heat_feat, W_heat, b_heat, t1);  // proj_heat
    gemv_stage<<<256, 256>>>(t1, Wv, bv, t2);                 // v
    gemv_stage<<<256, 256>>>(t2, Wo, bo, a);                  // attn_out per b
    // out = LN(img + a[b]) * gamma + beta
    add_ln_kernel<<<(NROWS / 2) / 8, 256>>>(img_feat, gamma, beta, out);
}

// round 11
// speedup vs baseline: 1.1835x; 1.1835x over previous
#include <cuda_runtime.h>
#include <cuda_bf16.h>

#define E_DIM 1024
#define B_DIM 32
#define NROWS (B_DIM * 1024)

// Scratch (no allocation allowed): intermediates of the 3-stage GEMV chain.
__device__ float g_t1[B_DIM * E_DIM];   // proj_heat
__device__ float g_t2[B_DIM * E_DIM];   // v
__device__ float g_a [B_DIM * E_DIM];   // attn_out per batch (broadcast over S)

// y[b,e] = sum_k x[b,k] * W[e,k] + bias[e]
// Grid 128 blocks x 256 thr. Block = 32 e-columns x 8 batches (one quarter of
// B). The x-quarter (32KB) is staged in SMEM once, so x reuse is guaranteed
// (not left to L1, which thrashed in R10). Each warp register-blocks 4 e's:
// per iter 4 W LDG.128 + 8 conflict-free x LDS.128 + 128 FMA/lane.
// W is read once per batch-quarter -> 16MB L2/stage (vs 128MB before).
// FMA floor per block ~4096 cyc => ~2.2us/stage.
__global__ __launch_bounds__(256) void gemv_stage(
    const float* __restrict__ x,
    const float* __restrict__ W,
    const float* __restrict__ bias,
    float* __restrict__ y)
{
    __shared__ float4 xs[8 * 256];            // 8 batches x 1024 floats = 32KB
    const int lane = threadIdx.x & 31;
    const int warp = threadIdx.x >> 5;
    const int bq = blockIdx.x & 3;            // batch quarter
    const int eg = blockIdx.x >> 2;           // e-group (0..31)
    const int b0 = bq * 8;
    const int e0 = eg * 32 + warp * 4;

    // Stage x quarter into smem (coalesced LDG.128 -> STS.128)
    const float4* __restrict__ xg = (const float4*)x + (size_t)b0 * 256;
#pragma unroll
    for (int i = 0; i < 8; i++)
        xs[threadIdx.x + 256 * i] = xg[threadIdx.x + 256 * i];
    __syncthreads();

    const float4* __restrict__ w4 = (const float4*)W + (size_t)e0 * 256;

    float acc[4][8];
#pragma unroll
    for (int j = 0; j < 4; j++)
#pragma unroll
        for (int b = 0; b < 8; b++) acc[j][b] = 0.0f;

#pragma unroll
    for (int i = 0; i < 8; i++) {
        const int idx = lane + 32 * i;
        float4 wv0 = w4[idx];
        float4 wv1 = w4[256 + idx];
        float4 wv2 = w4[512 + idx];
        float4 wv3 = w4[768 + idx];
#pragma unroll
        for (int b = 0; b < 8; b++) {
            float4 xv = xs[b * 256 + idx];   // lanes -> consecutive float4: conflict-free
            acc[0][b] += xv.x * wv0.x + xv.y * wv0.y + xv.z * wv0.z + xv.w * wv0.w;
            acc[1][b] += xv.x * wv1.x + xv.y * wv1.y + xv.z * wv1.z + xv.w * wv1.w;
            acc[2][b] += xv.x * wv2.x + xv.y * wv2.y + xv.z * wv2.z + xv.w * wv2.w;
            acc[3][b] += xv.x * wv3.x + xv.y * wv3.y + xv.z * wv3.z + xv.w * wv3.w;
        }
    }

    // Butterfly-reduce 32 independent accumulators across the warp.
#pragma unroll
    for (int off = 16; off; off >>= 1)
#pragma unroll
        for (int j = 0; j < 4; j++)
#pragma unroll
            for (int b = 0; b < 8; b++)
                acc[j][b] += __shfl_xor_sync(0xFFFFFFFFu, acc[j][b], off);

    if (lane == 0) {
#pragma unroll
        for (int j = 0; j < 4; j++) {
            const float bi = bias[e0 + j];
#pragma unroll
            for (int b = 0; b < 8; b++)
                y[(size_t)(b0 + b) * E_DIM + (e0 + j)] = acc[j][b] + bi;
        }
    }
}

// out[r,:] = LN(img[r,:] + a[b,:]) * gamma + beta.
// Block-per-row, 256 threads, ONE float4 per thread held in registers (~35
// regs -> 6-8 blocks/SM, 48-64 warps/SM for DRAM pressure). Single barrier:
// warp leaders write partials; every thread sums the 8 partials itself
// (broadcast smem reads), no second barrier. var = E[x^2]-mu^2 (validated
// rel_err ~2e-7 in R10).
__global__ __launch_bounds__(256) void add_ln_kernel(
    const float* __restrict__ img,
    const float* __restrict__ gamma,
    const float* __restrict__ beta,
    float* __restrict__ out)
{
    __shared__ float red_s[8], red_ss[8];
    const int r = blockIdx.x;
    const int b = r >> 10;
    const int t = threadIdx.x;
    const int lane = t & 31, wid = t >> 5;

    float4 u  = ((const float4*)img)[(size_t)r * 256 + t];
    float4 av = ((const float4*)g_a)[(size_t)b * 256 + t];  // 4KB/batch, L1-hot
    float4 gv = ((const float4*)gamma)[t];                  // L1-hot
    float4 bv = ((const float4*)beta)[t];                   // L1-hot
    u.x += av.x; u.y += av.y; u.z += av.z; u.w += av.w;

    float s  = u.x + u.y + u.z + u.w;
    float ss = u.x * u.x + u.y * u.y + u.z * u.z + u.w * u.w;
#pragma unroll
    for (int off = 16; off; off >>= 1) {
        s  += __shfl_xor_sync(0xFFFFFFFFu, s,  off);
        ss += __shfl_xor_sync(0xFFFFFFFFu, ss, off);
    }
    if (lane == 0) { red_s[wid] = s; red_ss[wid] = ss; }
    __syncthreads();

    float st = 0.f, sst = 0.f;
#pragma unroll
    for (int i = 0; i < 8; i++) { st += red_s[i]; sst += red_ss[i]; }
    const float inv_n = 1.0f / (float)E_DIM;
    const float mu = st * inv_n;
    const float ri = rsqrtf(sst * inv_n - mu * mu + 1e-5f);

    float4 o;
    o.x = (u.x - mu) * ri * gv.x + bv.x;
    o.y = (u.y - mu) * ri * gv.y + bv.y;
    o.z = (u.z - mu) * ri * gv.z + bv.z;
    o.w = (u.w - mu) * ri * gv.w + bv.w;
    ((float4*)out)[(size_t)r * 256 + t] = o;
}

// Inputs: 0 img_feat, 1 heat_feat, 2 W_img, 3 b_img, 4 W_heat, 5 b_heat,
// 6 Wq, 7 bq, 8 Wk, 9 bk, 10 Wv, 11 bv, 12 Wo, 13 bo, 14 gamma, 15 beta.
// KV seq len == 1 -> softmax == 1 -> img/Q projections are dead code, and
// attn_out is one vector per batch broadcast over all S tokens.
extern "C" void kernel_launch(void* const* d_in, const int* in_sizes, int n_in,
                              void* d_out, int out_size)
{
    const float* img_feat  = (const float*)d_in[0];
    const float* heat_feat = (const float*)d_in[1];
    const float* W_heat    = (const float*)d_in[4];
    const float* b_heat    = (const float*)d_in[5];
    const float* Wv        = (const float*)d_in[10];
    const float* bv        = (const float*)d_in[11];
    const float* Wo        = (const float*)d_in[12];
    const float* bo        = (const float*)d_in[13];
    const float* gamma     = (const float*)d_in[14];
    const float* beta      = (const float*)d_in[15];
    float* out = (float*)d_out;

    float *t1, *t2, *a;
    cudaGetSymbolAddress((void**)&t1, g_t1);
    cudaGetSymbolAddress((void**)&t2, g_t2);
    cudaGetSymbolAddress((void**)&a,  g_a);

    // 3 dependent GEMV stages; stream ordering is the synchronization.
    gemv_stage<<<128, 256>>>(heat_feat, W_heat, b_heat, t1);  // proj_heat
    gemv_stage<<<128, 256>>>(t1, Wv, bv, t2);                 // v
    gemv_stage<<<128, 256>>>(t2, Wo, bo, a);                  // attn_out per b
    // out = LN(img + a[b]) * gamma + beta
    add_ln_kernel<<<NROWS, 256>>>(img_feat, gamma, beta, out);
}

// round 13
// speedup vs baseline: 1.2166x; 1.0279x over previous
#include <cuda_runtime.h>
#include <cuda_bf16.h>

#define E_DIM 1024
#define B_DIM 32
#define NROWS (B_DIM * 1024)

// Scratch (no allocation allowed): intermediates of the 3-stage GEMV chain.
__device__ float g_t1[B_DIM * E_DIM];   // proj_heat
__device__ float g_t2[B_DIM * E_DIM];   // v
__device__ float g_a [B_DIM * E_DIM];   // attn_out per batch (broadcast over S)

// y[b,e] = sum_k x[b,k] * W[e,k] + bias[e]
// Grid 256 blocks (2/SM) x 256 thr. Block = 16 e-columns x 8 batches; the
// x 8-batch slab (32KB) is staged in SMEM (guaranteed reuse; L1 thrashed in
// R10). Each warp register-blocks 2 e's x 8 b's: per iter 2 W LDG.128 +
// 8 conflict-free LDS.128 + 64 FFMA/lane. 512 FFMA/lane total; 2 blocks/SM
// doubles latency-hiding warps vs R11 and shrinks the tail.
__global__ __launch_bounds__(256) void gemv_stage(
    const float* __restrict__ x,
    const float* __restrict__ W,
    const float* __restrict__ bias,
    float* __restrict__ y)
{
    __shared__ float4 xs[8 * 256];            // 8 batches x 1024 floats = 32KB
    const int lane = threadIdx.x & 31;
    const int warp = threadIdx.x >> 5;
    const int bq = blockIdx.x & 3;            // batch quarter (8 batches)
    const int eg = blockIdx.x >> 2;           // e-group (0..63)
    const int b0 = bq * 8;
    const int e0 = eg * 16 + warp * 2;

    // Stage x slab into smem (coalesced LDG.128 -> STS.128)
    const float4* __restrict__ xg = (const float4*)x + (size_t)b0 * 256;
#pragma unroll
    for (int i = 0; i < 8; i++)
        xs[threadIdx.x + 256 * i] = xg[threadIdx.x + 256 * i];
    __syncthreads();

    const float4* __restrict__ w4 = (const float4*)W + (size_t)e0 * 256;

    float acc0[8], acc1[8];
#pragma unroll
    for (int b = 0; b < 8; b++) { acc0[b] = 0.0f; acc1[b] = 0.0f; }

#pragma unroll
    for (int i = 0; i < 8; i++) {
        const int idx = lane + 32 * i;
        float4 wv0 = w4[idx];
        float4 wv1 = w4[256 + idx];
#pragma unroll
        for (int b = 0; b < 8; b++) {
            float4 xv = xs[b * 256 + idx];   // consecutive float4 per lane: conflict-free
            acc0[b] += xv.x * wv0.x + xv.y * wv0.y + xv.z * wv0.z + xv.w * wv0.w;
            acc1[b] += xv.x * wv1.x + xv.y * wv1.y + xv.z * wv1.z + xv.w * wv1.w;
        }
    }

#pragma unroll
    for (int off = 16; off; off >>= 1)
#pragma unroll
        for (int b = 0; b < 8; b++) {
            acc0[b] += __shfl_xor_sync(0xFFFFFFFFu, acc0[b], off);
            acc1[b] += __shfl_xor_sync(0xFFFFFFFFu, acc1[b], off);
        }

    if (lane == 0) {
        const float bi0 = bias[e0], bi1 = bias[e0 + 1];
#pragma unroll
        for (int b = 0; b < 8; b++) {
            y[(size_t)(b0 + b) * E_DIM + e0]     = acc0[b] + bi0;
            y[(size_t)(b0 + b) * E_DIM + e0 + 1] = acc1[b] + bi1;
        }
    }
}

// out[r,:] = LN(img[r,:] + a[b,:]) * gamma + beta.
// Thread-per-column, 16 rows per block (all same batch b): a/gamma/beta live
// in REGISTERS (loaded once) so per row each thread moves only 1 LDG.128 +
// 1 STG.128 through l1tex -- the R11 L1 bottleneck (74%) drops to ~DRAM
// parity. Per-row reduction: warp shuffle -> lane0 STS.64 -> ONE barrier
// (double-buffered partials) -> 8 broadcast LDS.64 per thread. Next row's img
// is prefetched before the barrier. var = E[x^2]-mu^2 (validated ~2e-7).
__global__ __launch_bounds__(256) void add_ln_kernel(
    const float* __restrict__ img,
    const float* __restrict__ gamma,
    const float* __restrict__ beta,
    float* __restrict__ out)
{
    __shared__ float2 part[2][8];
    const int t = threadIdx.x;
    const int lane = t & 31, wid = t >> 5;
    const int r0 = blockIdx.x * 16;           // 16 rows, same batch
    const int b  = r0 >> 10;

    const float4 av = ((const float4*)g_a)[(size_t)b * 256 + t];
    const float4 gv = ((const float4*)gamma)[t];
    const float4 bv = ((const float4*)beta)[t];
    const float inv_n = 1.0f / (float)E_DIM;

    const float4* __restrict__ xg = (const float4*)img + (size_t)r0 * 256 + t;
    float4*       __restrict__ og = (float4*)out       + (size_t)r0 * 256 + t;

    float4 nxt = xg[0];
#pragma unroll
    for (int r = 0; r < 16; r++) {
        float4 u = nxt;
        if (r < 15) nxt = xg[(r + 1) * 256];   // prefetch overlaps reduction
        u.x += av.x; u.y += av.y; u.z += av.z; u.w += av.w;

        float s  = u.x + u.y + u.z + u.w;
        float ss = u.x * u.x + u.y * u.y + u.z * u.z + u.w * u.w;
#pragma unroll
        for (int off = 16; off; off >>= 1) {
            s  += __shfl_xor_sync(0xFFFFFFFFu, s,  off);
            ss += __shfl_xor_sync(0xFFFFFFFFu, ss, off);
        }
        if (lane == 0) part[r & 1][wid] = make_float2(s, ss);
        __syncthreads();

        float st = 0.f, sst = 0.f;
#pragma unroll
        for (int i = 0; i < 8; i++) {
            float2 p = part[r & 1][i];         // smem broadcast
            st += p.x; sst += p.y;
        }
        const float mu = st * inv_n;
        const float ri = rsqrtf(sst * inv_n - mu * mu + 1e-5f);

        float4 o;
        o.x = (u.x - mu) * ri * gv.x + bv.x;
        o.y = (u.y - mu) * ri * gv.y + bv.y;
        o.z = (u.z - mu) * ri * gv.z + bv.z;
        o.w = (u.w - mu) * ri * gv.w + bv.w;
        og[r * 256] = o;
        // No second barrier: row r+2 overwrites part[r&1] only after the
        // r+1 barrier, which orders it after every thread's reads above.
    }
}

// Inputs: 0 img_feat, 1 heat_feat, 2 W_img, 3 b_img, 4 W_heat, 5 b_heat,
// 6 Wq, 7 bq, 8 Wk, 9 bk, 10 Wv, 11 bv, 12 Wo, 13 bo, 14 gamma, 15 beta.
// KV seq len == 1 -> softmax == 1 -> img/Q projections are dead code, and
// attn_out is one vector per batch broadcast over all S tokens.
extern "C" void kernel_launch(void* const* d_in, const int* in_sizes, int n_in,
                              void* d_out, int out_size)
{
    const float* img_feat  = (const float*)d_in[0];
    const float* heat_feat = (const float*)d_in[1];
    const float* W_heat    = (const float*)d_in[4];
    const float* b_heat    = (const float*)d_in[5];
    const float* Wv        = (const float*)d_in[10];
    const float* bv        = (const float*)d_in[11];
    const float* Wo        = (const float*)d_in[12];
    const float* bo        = (const float*)d_in[13];
    const float* gamma     = (const float*)d_in[14];
    const float* beta      = (const float*)d_in[15];
    float* out = (float*)d_out;

    float *t1, *t2, *a;
    cudaGetSymbolAddress((void**)&t1, g_t1);
    cudaGetSymbolAddress((void**)&t2, g_t2);
    cudaGetSymbolAddress((void**)&a,  g_a);

    // 3 dependent GEMV stages; stream ordering is the synchronization.
    gemv_stage<<<256, 256>>>(heat_feat, W_heat, b_heat, t1);  // proj_heat
    gemv_stage<<<256, 256>>>(t1, Wv, bv, t2);                 // v
    gemv_stage<<<256, 256>>>(t2, Wo, bo, a);                  // attn_out per b
    // out = LN(img + a[b]) * gamma + beta
    add_ln_kernel<<<NROWS / 16, 256>>>(img_feat, gamma, beta, out);
}

// round 14
// speedup vs baseline: 1.3304x; 1.0935x over previous
#include <cuda_runtime.h>
#include <cuda_bf16.h>

#define E_DIM 1024
#define B_DIM 32
#define NROWS (B_DIM * 1024)

// Scratch (no allocation allowed): intermediates of the 3-stage GEMV chain.
__device__ float g_t1[B_DIM * E_DIM];   // proj_heat
__device__ float g_t2[B_DIM * E_DIM];   // v
__device__ float g_a [B_DIM * E_DIM];   // attn_out per batch (broadcast over S)

__device__ __forceinline__ void stg_cs(float4* p, float4 v) {
    // Streaming store: out is write-once, never re-read -> evict-first in L2
    // so img keeps more L2 residency across graph replays.
    asm volatile("st.global.cs.v4.f32 [%0], {%1,%2,%3,%4};"
                 :: "l"(p), "f"(v.x), "f"(v.y), "f"(v.z), "f"(v.w) : "memory");
}

// y[b,e] = sum_k x[b,k] * W[e,k] + bias[e]
// Grid 256 (2/SM) x 256 thr; block = 16 e x 8 batches; x slab staged in smem.
// KEY CHANGE vs R13: all 16 W-row LDG.128 are issued into REGISTERS BEFORE the
// x staging + barrier. W is DRAM-cold every replay (LN's 256MB stream evicts
// L2), and previously those loads sat behind the barrier, serializing ~600cyc
// DRAM latency after staging. Now W latency overlaps the staging phase.
__global__ __launch_bounds__(256) void gemv_stage(
    const float* __restrict__ x,
    const float* __restrict__ W,
    const float* __restrict__ bias,
    float* __restrict__ y)
{
    __shared__ float4 xs[8 * 256];            // 8 batches x 1024 floats = 32KB
    const int lane = threadIdx.x & 31;
    const int warp = threadIdx.x >> 5;
    const int bq = blockIdx.x & 3;            // batch quarter (8 batches)
    const int eg = blockIdx.x >> 2;           // e-group (0..63)
    const int b0 = bq * 8;
    const int e0 = eg * 16 + warp * 2;

    // ---- 1. Issue all W loads first (16 independent LDG.128, high MLP) ----
    const float4* __restrict__ w4 = (const float4*)W + (size_t)e0 * 256;
    float4 wv0[8], wv1[8];
#pragma unroll
    for (int i = 0; i < 8; i++) {
        wv0[i] = w4[lane + 32 * i];
        wv1[i] = w4[256 + lane + 32 * i];
    }

    // ---- 2. Stage x slab into smem (overlaps W DRAM latency) ----
    const float4* __restrict__ xg = (const float4*)x + (size_t)b0 * 256;
#pragma unroll
    for (int i = 0; i < 8; i++)
        xs[threadIdx.x + 256 * i] = xg[threadIdx.x + 256 * i];
    __syncthreads();

    // ---- 3. Compute: W from registers, x from smem (conflict-free) ----
    float acc0[8], acc1[8];
#pragma unroll
    for (int b = 0; b < 8; b++) { acc0[b] = 0.0f; acc1[b] = 0.0f; }

#pragma unroll
    for (int i = 0; i < 8; i++) {
        const int idx = lane + 32 * i;
#pragma unroll
        for (int b = 0; b < 8; b++) {
            float4 xv = xs[b * 256 + idx];
            acc0[b] += xv.x * wv0[i].x + xv.y * wv0[i].y + xv.z * wv0[i].z + xv.w * wv0[i].w;
            acc1[b] += xv.x * wv1[i].x + xv.y * wv1[i].y + xv.z * wv1[i].z + xv.w * wv1[i].w;
        }
    }

#pragma unroll
    for (int off = 16; off; off >>= 1)
#pragma unroll
        for (int b = 0; b < 8; b++) {
            acc0[b] += __shfl_xor_sync(0xFFFFFFFFu, acc0[b], off);
            acc1[b] += __shfl_xor_sync(0xFFFFFFFFu, acc1[b], off);
        }

    if (lane == 0) {
        const float bi0 = bias[e0], bi1 = bias[e0 + 1];
#pragma unroll
        for (int b = 0; b < 8; b++) {
            y[(size_t)(b0 + b) * E_DIM + e0]     = acc0[b] + bi0;
            y[(size_t)(b0 + b) * E_DIM + e0 + 1] = acc1[b] + bi1;
        }
    }
}

// out[r,:] = LN(img[r,:] + a[b,:]) * gamma + beta.
// R6 design (best measured: 43.5us @ 63.7% DRAM): warp-per-row, row held in
// registers, shuffle-only reductions, zero barriers. Added: streaming stores
// for out (evict-first -> img keeps L2 across replays).
__global__ __launch_bounds__(256) void add_ln_kernel(
    const float* __restrict__ img,
    const float* __restrict__ gamma,
    const float* __restrict__ beta,
    float* __restrict__ out)
{
    const int lane = threadIdx.x & 31;
    const int r = blockIdx.x * 8 + (threadIdx.x >> 5);  // 0 .. 32767
    const int b = r >> 10;

    const float4* __restrict__ xr = (const float4*)img + (size_t)r * 256;
    const float4* __restrict__ ar = (const float4*)g_a + (size_t)b * 256;

    float4 v[8];
    float s = 0.0f, ss = 0.0f;
#pragma unroll
    for (int i = 0; i < 8; i++) {
        const int idx = lane + 32 * i;
        float4 xv = xr[idx];
        float4 av = ar[idx];               // 4KB/batch, L1/L2-hot
        xv.x += av.x; xv.y += av.y; xv.z += av.z; xv.w += av.w;
        v[i] = xv;
        s  += xv.x + xv.y + xv.z + xv.w;
        ss += xv.x * xv.x + xv.y * xv.y + xv.z * xv.z + xv.w * xv.w;
    }
#pragma unroll
    for (int off = 16; off; off >>= 1) {
        s  += __shfl_xor_sync(0xFFFFFFFFu, s,  off);
        ss += __shfl_xor_sync(0xFFFFFFFFu, ss, off);
    }
    const float inv_n = 1.0f / (float)E_DIM;
    const float mu = s * inv_n;
    const float ri = rsqrtf(ss * inv_n - mu * mu + 1e-5f);  // validated ~2e-7

    float4* __restrict__ orow = (float4*)out + (size_t)r * 256;
    const float4* __restrict__ g4 = (const float4*)gamma;
    const float4* __restrict__ b4 = (const float4*)beta;
#pragma unroll
    for (int i = 0; i < 8; i++) {
        const int idx = lane + 32 * i;
        float4 gv = g4[idx];
        float4 bv = b4[idx];
        float4 o;
        o.x = (v[i].x - mu) * ri * gv.x + bv.x;
        o.y = (v[i].y - mu) * ri * gv.y + bv.y;
        o.z = (v[i].z - mu) * ri * gv.z + bv.z;
        o.w = (v[i].w - mu) * ri * gv.w + bv.w;
        stg_cs(orow + idx, o);
    }
}

// Inputs: 0 img_feat, 1 heat_feat, 2 W_img, 3 b_img, 4 W_heat, 5 b_heat,
// 6 Wq, 7 bq, 8 Wk, 9 bk, 10 Wv, 11 bv, 12 Wo, 13 bo, 14 gamma, 15 beta.
// KV seq len == 1 -> softmax == 1 -> img/Q projections are dead code, and
// attn_out is one vector per batch broadcast over all S tokens.
extern "C" void kernel_launch(void* const* d_in, const int* in_sizes, int n_in,
                              void* d_out, int out_size)
{
    const float* img_feat  = (const float*)d_in[0];
    const float* heat_feat = (const float*)d_in[1];
    const float* W_heat    = (const float*)d_in[4];
    const float* b_heat    = (const float*)d_in[5];
    const float* Wv        = (const float*)d_in[10];
    const float* bv        = (const float*)d_in[11];
    const float* Wo        = (const float*)d_in[12];
    const float* bo        = (const float*)d_in[13];
    const float* gamma     = (const float*)d_in[14];
    const float* beta      = (const float*)d_in[15];
    float* out = (float*)d_out;

    float *t1, *t2, *a;
    cudaGetSymbolAddress((void**)&t1, g_t1);
    cudaGetSymbolAddress((void**)&t2, g_t2);
    cudaGetSymbolAddress((void**)&a,  g_a);

    // 3 dependent GEMV stages; stream ordering is the synchronization.
    gemv_stage<<<256, 256>>>(heat_feat, W_heat, b_heat, t1);  // proj_heat
    gemv_stage<<<256, 256>>>(t1, Wv, bv, t2);                 // v
    gemv_stage<<<256, 256>>>(t2, Wo, bo, a);                  // attn_out per b
    // out = LN(img + a[b]) * gamma + beta
    add_ln_kernel<<<NROWS / 8, 256>>>(img_feat, gamma, beta, out);
}